// round 5
// baseline (speedup 1.0000x reference)
#include <cuda_runtime.h>
#include <cstdint>

// Net_60413009985719 — collapsed net (no recurrence, only x[L-1] matters,
// LSTM f-gate dead). R5: keep TMA bulk weight loads; shorten the serial
// critical path: 2-lanes-per-row matvec (12 balanced warps, 4 accumulators,
// shfl combine), __expf-based activations, head-only staging deferred into
// the layer-0 activation window. One block, 512 threads.

#define H 64
#define ROWS 192          // live gate rows per layer (i, g, o; f is dead)
#define NT 512

// ---- shared layout (float offsets; float4-read regions 16B-aligned) ----
#define OFF_W    0                      // [4][192][64]
#define OFF_FC   (OFF_W + 4*ROWS*H)     // [32][64]
#define OFF_W0   (OFF_FC + 32*H)        // [192]
#define OFF_B0   (OFF_W0 + ROWS)        // [192]
#define OFF_BS   (OFF_B0 + ROWS)        // [4][192]
#define OFF_C1W  (OFF_BS + 4*ROWS)      // [16][32]
#define OFF_C1B  (OFF_C1W + 512)        // [16]
#define OFF_FCB  (OFF_C1B + 16)         // [32]
#define OFF_MW   (OFF_FCB + 32)         // [32]
#define OFF_LSW  (OFF_MW + 32)          // [32]
#define OFF_C2W  (OFF_LSW + 32)         // [16]
#define OFF_SC   (OFF_C2W + 16)         // [3] mean_b, ls_b, c2_b
#define OFF_H    (((OFF_SC + 3) + 3) & ~3)  // [64], 16B-aligned
#define OFF_G    (OFF_H + H)            // [192]
#define OFF_Z    (OFF_G + ROWS)         // [32]
#define OFF_VH   (OFF_Z + 32)           // [16]
#define OFF_SCAL (OFF_VH + 16)          // [2]
#define OFF_MBAR (((OFF_SCAL + 2) + 1) & ~1)   // 8B-aligned; 5 x u64
#define SMEM_FLOATS (OFF_MBAR + 10)
#define SMEM_BYTES  (SMEM_FLOATS * 4)

static_assert((OFF_H % 4) == 0, "h vector must be 16B-aligned");
static_assert((OFF_W % 4) == 0 && (H % 4) == 0, "W rows must be 16B-aligned");
static_assert((OFF_FC % 4) == 0, "fc rows must be 16B-aligned");
static_assert((OFF_MBAR % 2) == 0, "mbarrier must be 8B-aligned");

// fast activations: __expf / __fdividef (~1e-7 rel err; budget is 1e-3)
__device__ __forceinline__ float fsig(float x) {
    return __fdividef(1.0f, 1.0f + __expf(-x));
}
__device__ __forceinline__ float ftanh(float x) {
    float ax = fabsf(x);
    float e  = __expf(-2.0f * ax);            // in (0,1], no overflow
    float t  = __fdividef(1.0f - e, 1.0f + e);
    return copysignf(t, x);
}

__device__ __forceinline__ void mbar_init(uint32_t addr, uint32_t count) {
    asm volatile("mbarrier.init.shared.b64 [%0], %1;" :: "r"(addr), "r"(count) : "memory");
}
__device__ __forceinline__ void mbar_expect(uint32_t addr, uint32_t bytes) {
    asm volatile("mbarrier.arrive.expect_tx.shared.b64 _, [%0], %1;"
                 :: "r"(addr), "r"(bytes) : "memory");
}
__device__ __forceinline__ void bulk_g2s(uint32_t dst, const void* src,
                                         uint32_t bytes, uint32_t mbar) {
    asm volatile("cp.async.bulk.shared::cta.global.mbarrier::complete_tx::bytes "
                 "[%0], [%1], %2, [%3];"
                 :: "r"(dst), "l"(src), "r"(bytes), "r"(mbar) : "memory");
}
__device__ __forceinline__ void mbar_wait0(uint32_t addr) {
    asm volatile(
        "{\n\t"
        ".reg .pred P;\n\t"
        "WAIT_%=:\n\t"
        "mbarrier.try_wait.parity.acquire.cta.shared::cta.b64 P, [%0], 0, 0x989680;\n\t"
        "@P bra.uni DONE_%=;\n\t"
        "bra.uni WAIT_%=;\n\t"
        "DONE_%=:\n\t"
        "}" :: "r"(addr) : "memory");
}
__device__ __forceinline__ void fence_proxy_async_sc() {
    asm volatile("fence.proxy.async.shared::cta;" ::: "memory");
}

// lstm activation for index idx (0..63) from g[0..191] -> h[idx]
__device__ __forceinline__ void do_act(float* sm, int idx) {
    float iv = fsig(sm[OFF_G + idx]);
    float gv = ftanh(sm[OFF_G + 64 + idx]);
    float ov = fsig(sm[OFF_G + 128 + idx]);
    sm[OFF_H + idx] = ov * ftanh(iv * gv);
}

__global__ void __launch_bounds__(NT, 1)
net_kernel(const float* __restrict__ x, long long L,
           const float* __restrict__ Wih0,
           const float* __restrict__ bih0,
           const float* __restrict__ bhh0,
           const float* __restrict__ Wih,
           const float* __restrict__ bih,
           const float* __restrict__ bhh,
           const float* __restrict__ fc_w,
           const float* __restrict__ fc_b,
           const float* __restrict__ mean_w,
           const float* __restrict__ mean_b,
           const float* __restrict__ ls_w,
           const float* __restrict__ ls_b,
           const float* __restrict__ c1_w,
           const float* __restrict__ c1_b,
           const float* __restrict__ c2_w,
           const float* __restrict__ c2_b,
           float* __restrict__ out)
{
    extern __shared__ __align__(16) float sm[];
    const int tid = threadIdx.x;
    const uint32_t smbase = (uint32_t)__cvta_generic_to_shared(sm);
    const uint32_t mbar = smbase + OFF_MBAR * 4;
    const int aw = tid >> 5, al = tid & 31;

    // ---- 1) TMA bulk copies for all big weights ----
    if (tid == 0) {
        #pragma unroll
        for (int i = 0; i < 5; ++i) mbar_init(mbar + 8 * i, 1);
        fence_proxy_async_sc();
        #pragma unroll
        for (int l = 0; l < 4; ++l) {
            uint32_t mb = mbar + 8 * l;
            mbar_expect(mb, ROWS * H * 4);
            bulk_g2s(smbase + (OFF_W + (l * ROWS) * H) * 4,
                     Wih + (size_t)l * 256 * H, 64 * H * 4, mb);          // i rows
            bulk_g2s(smbase + (OFF_W + (l * ROWS + 64) * H) * 4,
                     Wih + ((size_t)l * 256 + 128) * H, 128 * H * 4, mb); // g+o rows
        }
        mbar_expect(mbar + 8 * 4, 32 * H * 4);
        bulk_g2s(smbase + OFF_FC * 4, fc_w, 32 * H * 4, mbar + 8 * 4);
    }

    // ---- 2) critical staging only: layer-0 weights + all biases ----
    const float xv = x[L - 1];
    if (tid < ROWS) {
        int grow = (tid < 64) ? tid : tid + 64;
        sm[OFF_W0 + tid] = Wih0[grow];
        sm[OFF_B0 + tid] = bih0[grow] + bhh0[grow];
    }
    for (int j = tid; j < 4 * ROWS; j += NT) {
        int l = j / ROWS, r = j - l * ROWS;
        int grow = (r < 64) ? r : r + 64;
        sm[OFF_BS + j] = bih[l * 256 + grow] + bhh[l * 256 + grow];
    }
    __syncthreads();   // staging + mbarrier init visible

    // ---- 3) layer 0: gates from scalar ----
    if (tid < ROWS) sm[OFF_G + tid] = xv * sm[OFF_W0 + tid] + sm[OFF_B0 + tid];
    __syncthreads();

    // layer-0 activation (spread over warps 0-3) ∥ deferred head staging
    if (aw < 4 && al < 16) {
        do_act(sm, aw * 16 + al);
    } else if (tid >= 128) {
        int u = tid - 128;                       // 0..383
        if (u < 32)       sm[OFF_FCB + u]       = fc_b[u];
        else if (u < 64)  sm[OFF_MW + u - 32]   = mean_w[u - 32];
        else if (u < 96)  sm[OFF_LSW + u - 64]  = ls_w[u - 64];
        else if (u < 112) sm[OFF_C1B + u - 96]  = c1_b[u - 96];
        else if (u < 128) sm[OFF_C2W + u - 112] = c2_w[u - 112];
        else if (u == 128) {
            sm[OFF_SC + 0] = mean_b[0];
            sm[OFF_SC + 1] = ls_b[0];
            sm[OFF_SC + 2] = c2_b[0];
        }
        for (int j = u; j < 512; j += 384) sm[OFF_C1W + j] = c1_w[j];
    }

    // ---- 4) layers 1..4: 2 lanes per row, 4 accumulators, shfl combine ----
    #pragma unroll
    for (int l = 0; l < 4; ++l) {
        mbar_wait0(mbar + 8 * l);
        __syncthreads();       // TMA data + h + (l==0: staging) visible
        if (tid < 384) {
            int row  = tid >> 1;          // 0..191
            int half = tid & 1;
            const float4* Wr = (const float4*)(sm + OFF_W + (l * ROWS + row) * H);
            const float4* hv = (const float4*)(sm + OFF_H);
            int base = half * 8;
            float a0 = 0.f, a1 = 0.f, a2 = 0.f, a3 = 0.f;
            #pragma unroll
            for (int j = 0; j < 8; j += 4) {
                int k0 = base + ((j + 0 + row) & 7);
                int k1 = base + ((j + 1 + row) & 7);
                int k2 = base + ((j + 2 + row) & 7);
                int k3 = base + ((j + 3 + row) & 7);
                float4 w0 = Wr[k0], h0 = hv[k0];
                float4 w1 = Wr[k1], h1 = hv[k1];
                float4 w2 = Wr[k2], h2 = hv[k2];
                float4 w3 = Wr[k3], h3 = hv[k3];
                a0 += w0.x * h0.x + w0.y * h0.y + w0.z * h0.z + w0.w * h0.w;
                a1 += w1.x * h1.x + w1.y * h1.y + w1.z * h1.z + w1.w * h1.w;
                a2 += w2.x * h2.x + w2.y * h2.y + w2.z * h2.z + w2.w * h2.w;
                a3 += w3.x * h3.x + w3.y * h3.y + w3.z * h3.z + w3.w * h3.w;
            }
            float acc = (a0 + a1) + (a2 + a3);
            acc += __shfl_down_sync(0xFFFFFFFFu, acc, 1);
            if (half == 0)
                sm[OFF_G + row] = acc + sm[OFF_BS + l * ROWS + row];
        }
        __syncthreads();
        if (aw < 4 && al < 16) do_act(sm, aw * 16 + al);
    }

    mbar_wait0(mbar + 8 * 4);  // fc weights
    __syncthreads();

    // ---- 5) head: z = relu(fc), 2 lanes per row ----
    if (tid < 64) {
        int row  = tid >> 1;          // 0..31
        int half = tid & 1;
        const float4* Wr = (const float4*)(sm + OFF_FC + row * H);
        const float4* hv = (const float4*)(sm + OFF_H);
        int base = half * 8;
        float a0 = 0.f, a1 = 0.f, a2 = 0.f, a3 = 0.f;
        #pragma unroll
        for (int j = 0; j < 8; j += 4) {
            int k0 = base + ((j + 0 + row) & 7);
            int k1 = base + ((j + 1 + row) & 7);
            int k2 = base + ((j + 2 + row) & 7);
            int k3 = base + ((j + 3 + row) & 7);
            float4 w0 = Wr[k0], h0 = hv[k0];
            float4 w1 = Wr[k1], h1 = hv[k1];
            float4 w2 = Wr[k2], h2 = hv[k2];
            float4 w3 = Wr[k3], h3 = hv[k3];
            a0 += w0.x * h0.x + w0.y * h0.y + w0.z * h0.z + w0.w * h0.w;
            a1 += w1.x * h1.x + w1.y * h1.y + w1.z * h1.z + w1.w * h1.w;
            a2 += w2.x * h2.x + w2.y * h2.y + w2.z * h2.z + w2.w * h2.w;
            a3 += w3.x * h3.x + w3.y * h3.y + w3.z * h3.z + w3.w * h3.w;
        }
        float acc = (a0 + a1) + (a2 + a3);
        acc += __shfl_down_sync(0xFFFFFFFFu, acc, 1);
        if (half == 0)
            sm[OFF_Z + row] = fmaxf(acc + sm[OFF_FCB + row], 0.0f);
    }
    __syncthreads();

    // ---- 6) tiny heads ----
    if (tid < 16) {
        const float* Wr = sm + OFF_C1W + tid * 32;
        float a0 = 0.f, a1 = 0.f, a2 = 0.f, a3 = 0.f;
        #pragma unroll
        for (int k = 0; k < 32; k += 4) {
            int k0 = (k + 0 + 2 * tid) & 31;
            int k1 = (k + 1 + 2 * tid) & 31;
            int k2 = (k + 2 + 2 * tid) & 31;
            int k3 = (k + 3 + 2 * tid) & 31;
            a0 += sm[OFF_Z + k0] * Wr[k0];
            a1 += sm[OFF_Z + k1] * Wr[k1];
            a2 += sm[OFF_Z + k2] * Wr[k2];
            a3 += sm[OFF_Z + k3] * Wr[k3];
        }
        sm[OFF_VH + tid] = fmaxf((a0 + a1) + (a2 + a3) + sm[OFF_C1B + tid], 0.0f);
    } else if (tid == 16 || tid == 17) {
        const float* Wv = sm + ((tid == 16) ? OFF_MW : OFF_LSW);
        float a0 = 0.f, a1 = 0.f, a2 = 0.f, a3 = 0.f;
        #pragma unroll
        for (int k = 0; k < 32; k += 4) {
            a0 += sm[OFF_Z + k + 0] * Wv[k + 0];
            a1 += sm[OFF_Z + k + 1] * Wv[k + 1];
            a2 += sm[OFF_Z + k + 2] * Wv[k + 2];
            a3 += sm[OFF_Z + k + 3] * Wv[k + 3];
        }
        sm[OFF_SCAL + (tid - 16)] = (a0 + a1) + (a2 + a3) + sm[OFF_SC + (tid - 16)];
    }
    __syncthreads();

    if (tid == 0) {
        float a0 = 0.f, a1 = 0.f;
        #pragma unroll
        for (int k = 0; k < 16; k += 2) {
            a0 += sm[OFF_VH + k]     * sm[OFF_C2W + k];
            a1 += sm[OFF_VH + k + 1] * sm[OFF_C2W + k + 1];
        }
        out[0] = sm[OFF_SCAL + 0];
        out[1] = sm[OFF_SCAL + 1];
        out[2] = a0 + a1 + sm[OFF_SC + 2];
    }
}

extern "C" void kernel_launch(void* const* d_in, const int* in_sizes, int n_in,
                              void* d_out, int out_size) {
    const float* x      = (const float*)d_in[0];
    const float* Wih0   = (const float*)d_in[1];
    const float* bih0   = (const float*)d_in[3];
    const float* bhh0   = (const float*)d_in[4];
    const float* Wih    = (const float*)d_in[5];
    const float* bih    = (const float*)d_in[7];
    const float* bhh    = (const float*)d_in[8];
    const float* fc_w   = (const float*)d_in[9];
    const float* fc_b   = (const float*)d_in[10];
    const float* mean_w = (const float*)d_in[11];
    const float* mean_b = (const float*)d_in[12];
    const float* ls_w   = (const float*)d_in[13];
    const float* ls_b   = (const float*)d_in[14];
    const float* c1_w   = (const float*)d_in[15];
    const float* c1_b   = (const float*)d_in[16];
    const float* c2_w   = (const float*)d_in[17];
    const float* c2_b   = (const float*)d_in[18];

    long long L = in_sizes[0];

    cudaFuncSetAttribute(net_kernel,
                         cudaFuncAttributeMaxDynamicSharedMemorySize, SMEM_BYTES);

    net_kernel<<<1, NT, SMEM_BYTES>>>(x, L, Wih0, bih0, bhh0, Wih, bih, bhh,
                                      fc_w, fc_b, mean_w, mean_b, ls_w, ls_b,
                                      c1_w, c1_b, c2_w, c2_b, (float*)d_out);
}

// round 6
// speedup vs baseline: 1.1066x; 1.1066x over previous
#include <cuda_runtime.h>
#include <cstdint>

// Net_60413009985719 — collapsed net (no recurrence, only x[L-1] matters,
// LSTM f-gate dead). R6 = R4 skeleton (TMA bulk weight loads, 1 row/thread
// float4 matvec) with serial-chain cuts only:
//  - biases + layer-0 weights preloaded to REGISTERS (no staging phase)
//  - mbarrier polls hidden in act windows via designated waiter (tid 192)
//  - 4 accumulators in the matvec (chain 256 -> ~70 cyc)
//  - __expf activations
//  - head staging on idle threads; NT=256

#define H 64
#define ROWS 192          // live gate rows per layer (i, g, o; f is dead)
#define NT 256

// ---- shared layout (float offsets; float4-read regions 16B-aligned) ----
#define OFF_W    0                      // [4][192][64]
#define OFF_FC   (OFF_W + 4*ROWS*H)     // [32][64]
#define OFF_C1W  (OFF_FC + 32*H)        // [16][32]
#define OFF_MW   (OFF_C1W + 512)        // [32]
#define OFF_LSW  (OFF_MW + 32)          // [32]
#define OFF_C2W  (OFF_LSW + 32)         // [16]
#define OFF_SC   (OFF_C2W + 16)         // [3] mean_b, ls_b, c2_b
#define OFF_H    (((OFF_SC + 3) + 3) & ~3)  // [64], 16B-aligned
#define OFF_G    (OFF_H + H)            // [192]
#define OFF_Z    (OFF_G + ROWS)         // [32]
#define OFF_VH   (OFF_Z + 32)           // [16]
#define OFF_SCAL (OFF_VH + 16)          // [2]
#define OFF_MBAR (((OFF_SCAL + 2) + 1) & ~1)   // 8B-aligned; 5 x u64
#define SMEM_FLOATS (OFF_MBAR + 10)
#define SMEM_BYTES  (SMEM_FLOATS * 4)

static_assert((OFF_H % 4) == 0, "h vector must be 16B-aligned");
static_assert((OFF_W % 4) == 0 && (H % 4) == 0, "W rows must be 16B-aligned");
static_assert((OFF_FC % 4) == 0, "fc rows must be 16B-aligned");
static_assert((OFF_MBAR % 2) == 0, "mbarrier must be 8B-aligned");

__device__ __forceinline__ float fsig(float x) {
    return __fdividef(1.0f, 1.0f + __expf(-x));
}
__device__ __forceinline__ float ftanh(float x) {
    float ax = fabsf(x);
    float e  = __expf(-2.0f * ax);
    float t  = __fdividef(1.0f - e, 1.0f + e);
    return copysignf(t, x);
}

__device__ __forceinline__ void mbar_init(uint32_t addr, uint32_t count) {
    asm volatile("mbarrier.init.shared.b64 [%0], %1;" :: "r"(addr), "r"(count) : "memory");
}
__device__ __forceinline__ void mbar_expect(uint32_t addr, uint32_t bytes) {
    asm volatile("mbarrier.arrive.expect_tx.shared.b64 _, [%0], %1;"
                 :: "r"(addr), "r"(bytes) : "memory");
}
__device__ __forceinline__ void bulk_g2s(uint32_t dst, const void* src,
                                         uint32_t bytes, uint32_t mbar) {
    asm volatile("cp.async.bulk.shared::cta.global.mbarrier::complete_tx::bytes "
                 "[%0], [%1], %2, [%3];"
                 :: "r"(dst), "l"(src), "r"(bytes), "r"(mbar) : "memory");
}
__device__ __forceinline__ void mbar_wait0(uint32_t addr) {
    asm volatile(
        "{\n\t"
        ".reg .pred P;\n\t"
        "WAIT_%=:\n\t"
        "mbarrier.try_wait.parity.acquire.cta.shared::cta.b64 P, [%0], 0, 0x989680;\n\t"
        "@P bra.uni DONE_%=;\n\t"
        "bra.uni WAIT_%=;\n\t"
        "DONE_%=:\n\t"
        "}" :: "r"(addr) : "memory");
}
__device__ __forceinline__ void fence_proxy_async_sc() {
    asm volatile("fence.proxy.async.shared::cta;" ::: "memory");
}

// lstm activation for index idx (0..63): g[idx]=i, g[64+idx]=g, g[128+idx]=o
__device__ __forceinline__ void do_act(float* sm, int idx) {
    float iv = fsig(sm[OFF_G + idx]);
    float gv = ftanh(sm[OFF_G + 64 + idx]);
    float ov = fsig(sm[OFF_G + 128 + idx]);
    sm[OFF_H + idx] = ov * ftanh(iv * gv);
}

__global__ void __launch_bounds__(NT, 1)
net_kernel(const float* __restrict__ x, long long L,
           const float* __restrict__ Wih0,
           const float* __restrict__ bih0,
           const float* __restrict__ bhh0,
           const float* __restrict__ Wih,
           const float* __restrict__ bih,
           const float* __restrict__ bhh,
           const float* __restrict__ fc_w,
           const float* __restrict__ fc_b,
           const float* __restrict__ mean_w,
           const float* __restrict__ mean_b,
           const float* __restrict__ ls_w,
           const float* __restrict__ ls_b,
           const float* __restrict__ c1_w,
           const float* __restrict__ c1_b,
           const float* __restrict__ c2_w,
           const float* __restrict__ c2_b,
           float* __restrict__ out)
{
    extern __shared__ __align__(16) float sm[];
    const int tid = threadIdx.x;
    const uint32_t smbase = (uint32_t)__cvta_generic_to_shared(sm);
    const uint32_t mbar = smbase + OFF_MBAR * 4;

    // ---- 0) issue TMA for all big weights (thread 0) ----
    if (tid == 0) {
        #pragma unroll
        for (int i = 0; i < 5; ++i) mbar_init(mbar + 8 * i, 1);
        fence_proxy_async_sc();
        #pragma unroll
        for (int l = 0; l < 4; ++l) {
            uint32_t mb = mbar + 8 * l;
            mbar_expect(mb, ROWS * H * 4);
            bulk_g2s(smbase + (OFF_W + (l * ROWS) * H) * 4,
                     Wih + (size_t)l * 256 * H, 64 * H * 4, mb);          // i rows
            bulk_g2s(smbase + (OFF_W + (l * ROWS + 64) * H) * 4,
                     Wih + ((size_t)l * 256 + 128) * H, 128 * H * 4, mb); // g+o rows
        }
        mbar_expect(mbar + 8 * 4, 32 * H * 4);
        bulk_g2s(smbase + OFF_FC * 4, fc_w, 32 * H * 4, mbar + 8 * 4);
    }

    // ---- 1) register preloads (all LDGs issued up front, overlapped) ----
    const float xv = x[L - 1];                     // the only live input element
    float br[4];                                   // per-layer bias for my row
    float w0r = 0.f, b0r = 0.f, fcbr = 0.f, c1br = 0.f;
    if (tid < ROWS) {
        int grow = (tid < 64) ? tid : tid + 64;
        w0r = Wih0[grow];
        b0r = bih0[grow] + bhh0[grow];
        #pragma unroll
        for (int l = 0; l < 4; ++l)
            br[l] = bih[l * 256 + grow] + bhh[l * 256 + grow];
    }
    if (tid < 32) fcbr = fc_b[tid];
    if (tid < 16) c1br = c1_b[tid];

    // layer-0 gates straight from registers (no staging round-trip)
    if (tid < ROWS) sm[OFF_G + tid] = xv * w0r + b0r;
    __syncthreads();   // G0 + mbarrier inits visible

    // act window 0: act(h0) || waiter grabs layer-1 weights || head staging
    if (tid < 64) {
        do_act(sm, tid);
    } else if (tid == 192) {
        mbar_wait0(mbar + 0);                      // W layer-1
    } else if (tid > 192) {
        int u = tid - 193;                         // 0..62
        for (int j = u; j < 512; j += 63) sm[OFF_C1W + j] = c1_w[j];
        if (u < 32)       sm[OFF_MW + u]       = mean_w[u];
        else if (u == 62) {
            sm[OFF_SC + 0] = mean_b[0];
            sm[OFF_SC + 1] = ls_b[0];
            sm[OFF_SC + 2] = c2_b[0];
        }
        if (u < 16)       sm[OFF_C2W + u]      = c2_w[u];
        if (u >= 16 && u < 48) sm[OFF_LSW + u - 16] = ls_w[u - 16];
    }
    __syncthreads();   // h0 + TMA group 0 + head staging visible

    // ---- 2) layers 1..4: one row per thread, 4 accumulators ----
    #pragma unroll
    for (int l = 0; l < 4; ++l) {
        if (tid < ROWS) {
            const float4* Wr = (const float4*)(sm + OFF_W + (l * ROWS + tid) * H);
            const float4* hv = (const float4*)(sm + OFF_H);
            float a0 = 0.f, a1 = 0.f, a2 = 0.f, a3 = 0.f;
            #pragma unroll
            for (int j = 0; j < 16; j += 4) {
                int k0 = (j + 0 + tid) & 15;       // rotation: conflict-free
                int k1 = (j + 1 + tid) & 15;
                int k2 = (j + 2 + tid) & 15;
                int k3 = (j + 3 + tid) & 15;
                float4 w0 = Wr[k0], h0 = hv[k0];
                float4 w1 = Wr[k1], h1 = hv[k1];
                float4 w2 = Wr[k2], h2 = hv[k2];
                float4 w3 = Wr[k3], h3 = hv[k3];
                a0 += w0.x * h0.x + w0.y * h0.y + w0.z * h0.z + w0.w * h0.w;
                a1 += w1.x * h1.x + w1.y * h1.y + w1.z * h1.z + w1.w * h1.w;
                a2 += w2.x * h2.x + w2.y * h2.y + w2.z * h2.z + w2.w * h2.w;
                a3 += w3.x * h3.x + w3.y * h3.y + w3.z * h3.z + w3.w * h3.w;
            }
            sm[OFF_G + tid] = (a0 + a1) + (a2 + a3) + br[l];
        }
        __syncthreads();   // G visible
        // act window: act threads compute h; waiter grabs next TMA group
        if (tid < 64) {
            do_act(sm, tid);
        } else if (tid == 192) {
            mbar_wait0(mbar + 8 * (l + 1));        // l<3: next W; l==3: fc
        }
        __syncthreads();   // h + next-layer data visible
    }

    // ---- 3) head: z = relu(h @ fc_w.T + fc_b), one row per thread ----
    if (tid < 32) {
        const float4* Wr = (const float4*)(sm + OFF_FC + tid * H);
        const float4* hv = (const float4*)(sm + OFF_H);
        float a0 = 0.f, a1 = 0.f, a2 = 0.f, a3 = 0.f;
        #pragma unroll
        for (int j = 0; j < 16; j += 4) {
            int k0 = (j + 0 + tid) & 15;
            int k1 = (j + 1 + tid) & 15;
            int k2 = (j + 2 + tid) & 15;
            int k3 = (j + 3 + tid) & 15;
            float4 w0 = Wr[k0], h0 = hv[k0];
            float4 w1 = Wr[k1], h1 = hv[k1];
            float4 w2 = Wr[k2], h2 = hv[k2];
            float4 w3 = Wr[k3], h3 = hv[k3];
            a0 += w0.x * h0.x + w0.y * h0.y + w0.z * h0.z + w0.w * h0.w;
            a1 += w1.x * h1.x + w1.y * h1.y + w1.z * h1.z + w1.w * h1.w;
            a2 += w2.x * h2.x + w2.y * h2.y + w2.z * h2.z + w2.w * h2.w;
            a3 += w3.x * h3.x + w3.y * h3.y + w3.z * h3.z + w3.w * h3.w;
        }
        sm[OFF_Z + tid] = fmaxf((a0 + a1) + (a2 + a3) + fcbr, 0.0f);
    }
    __syncthreads();

    // ---- 4) tiny heads ----
    if (tid < 16) {
        const float* Wr = sm + OFF_C1W + tid * 32;
        float a0 = 0.f, a1 = 0.f, a2 = 0.f, a3 = 0.f;
        #pragma unroll
        for (int k = 0; k < 32; k += 4) {
            int k0 = (k + 0 + 2 * tid) & 31;
            int k1 = (k + 1 + 2 * tid) & 31;
            int k2 = (k + 2 + 2 * tid) & 31;
            int k3 = (k + 3 + 2 * tid) & 31;
            a0 += sm[OFF_Z + k0] * Wr[k0];
            a1 += sm[OFF_Z + k1] * Wr[k1];
            a2 += sm[OFF_Z + k2] * Wr[k2];
            a3 += sm[OFF_Z + k3] * Wr[k3];
        }
        sm[OFF_VH + tid] = fmaxf((a0 + a1) + (a2 + a3) + c1br, 0.0f);
    } else if (tid == 16 || tid == 17) {
        const float* Wv = sm + ((tid == 16) ? OFF_MW : OFF_LSW);
        float a0 = 0.f, a1 = 0.f, a2 = 0.f, a3 = 0.f;
        #pragma unroll
        for (int k = 0; k < 32; k += 4) {
            a0 += sm[OFF_Z + k + 0] * Wv[k + 0];
            a1 += sm[OFF_Z + k + 1] * Wv[k + 1];
            a2 += sm[OFF_Z + k + 2] * Wv[k + 2];
            a3 += sm[OFF_Z + k + 3] * Wv[k + 3];
        }
        sm[OFF_SCAL + (tid - 16)] = (a0 + a1) + (a2 + a3) + sm[OFF_SC + (tid - 16)];
    }
    __syncthreads();

    if (tid == 0) {
        float a0 = 0.f, a1 = 0.f;
        #pragma unroll
        for (int k = 0; k < 16; k += 2) {
            a0 += sm[OFF_VH + k]     * sm[OFF_C2W + k];
            a1 += sm[OFF_VH + k + 1] * sm[OFF_C2W + k + 1];
        }
        out[0] = sm[OFF_SCAL + 0];
        out[1] = sm[OFF_SCAL + 1];
        out[2] = a0 + a1 + sm[OFF_SC + 2];
    }
}

extern "C" void kernel_launch(void* const* d_in, const int* in_sizes, int n_in,
                              void* d_out, int out_size) {
    const float* x      = (const float*)d_in[0];
    const float* Wih0   = (const float*)d_in[1];
    const float* bih0   = (const float*)d_in[3];
    const float* bhh0   = (const float*)d_in[4];
    const float* Wih    = (const float*)d_in[5];
    const float* bih    = (const float*)d_in[7];
    const float* bhh    = (const float*)d_in[8];
    const float* fc_w   = (const float*)d_in[9];
    const float* fc_b   = (const float*)d_in[10];
    const float* mean_w = (const float*)d_in[11];
    const float* mean_b = (const float*)d_in[12];
    const float* ls_w   = (const float*)d_in[13];
    const float* ls_b   = (const float*)d_in[14];
    const float* c1_w   = (const float*)d_in[15];
    const float* c1_b   = (const float*)d_in[16];
    const float* c2_w   = (const float*)d_in[17];
    const float* c2_b   = (const float*)d_in[18];

    long long L = in_sizes[0];

    cudaFuncSetAttribute(net_kernel,
                         cudaFuncAttributeMaxDynamicSharedMemorySize, SMEM_BYTES);

    net_kernel<<<1, NT, SMEM_BYTES>>>(x, L, Wih0, bih0, bhh0, Wih, bih, bhh,
                                      fc_w, fc_b, mean_w, mean_b, ls_w, ls_b,
                                      c1_w, c1_b, c2_w, c2_b, (float*)d_out);
}